// round 2
// baseline (speedup 1.0000x reference)
#include <cuda_runtime.h>
#include <cstdint>

// Problem constants
#define VOCAB 50257
#define DIM   2048
#define RNK   64
#define DC    256      // d-columns per CTA
#define TC    64       // tokens per CTA
#define NTHREADS 256
#define BS_STRIDE 65   // padded stride for B smem tile (conflict-free)

// Blackwell packed fp32x2 FMA (only reachable via PTX; 2 FMAs per instruction)
__device__ __forceinline__ void fma2(unsigned long long& d,
                                     unsigned long long a,
                                     unsigned long long b) {
    asm("fma.rn.f32x2 %0, %1, %2, %0;" : "+l"(d) : "l"(a), "l"(b));
}

__device__ __forceinline__ unsigned long long pack2(float lo, float hi) {
    unsigned long long r;
    asm("mov.b64 %0, {%1, %2};" : "=l"(r) : "f"(lo), "f"(hi));
    return r;
}

__global__ void __launch_bounds__(NTHREADS)
lora_embed_kernel(const int* __restrict__ x,
                  const float* __restrict__ W,
                  const float* __restrict__ A,
                  const float* __restrict__ Bm,
                  float* __restrict__ out) {
    extern __shared__ float sm[];
    float* Bs = sm;                              // [DC][BS_STRIDE]
    float* As = sm + DC * BS_STRIDE;             // [RNK][TC]  (r-major, token contiguous)
    int*  toks = (int*)(As + RNK * TC);          // [TC]

    const int tid   = threadIdx.x;
    const int dBase = blockIdx.x * DC;
    const int tBase = blockIdx.y * TC;

    // ---- load tokens for this tile ----
    if (tid < TC) toks[tid] = x[tBase + tid];

    // ---- load B chunk [DC x RNK] into padded smem (coalesced gmem, cf smem) ----
    #pragma unroll 4
    for (int idx = tid; idx < DC * RNK; idx += NTHREADS) {
        int dl = idx >> 6;      // /RNK
        int r  = idx & 63;
        Bs[dl * BS_STRIDE + r] = Bm[(dBase + dl) * RNK + r];
    }
    __syncthreads();   // toks visible

    // ---- gather A columns: As[r][i] = A[r*VOCAB + toks[i]] (L2-resident 12.8MB) ----
    #pragma unroll 4
    for (int idx = tid; idx < RNK * TC; idx += NTHREADS) {
        int r = idx >> 6;       // /TC
        int i = idx & 63;
        As[r * TC + i] = A[(long)r * VOCAB + toks[i]];
    }
    __syncthreads();

    // ---- register-blocked GEMM: 8 tokens x 8 d per thread, f32x2 packed ----
    const int tx = tid & 31;    // d lane
    const int ty = tid >> 5;    // token group (0..7)
    const int t0 = ty * 8;      // first of 8 tokens for this thread

    unsigned long long acc[4][8];   // [token-pair][d]
    #pragma unroll
    for (int i = 0; i < 4; ++i)
        #pragma unroll
        for (int j = 0; j < 8; ++j) acc[i][j] = 0ull;

    #pragma unroll 4
    for (int r = 0; r < RNK; ++r) {
        // 4x LDS.64 broadcast loads: token pairs (t0+2i, t0+2i+1)
        unsigned long long a2[4];
        const unsigned long long* arow =
            (const unsigned long long*)(As + r * TC + t0);
        #pragma unroll
        for (int i = 0; i < 4; ++i) a2[i] = arow[i];

        #pragma unroll
        for (int j = 0; j < 8; ++j) {
            float b = Bs[(tx + j * 32) * BS_STRIDE + r];   // conflict-free
            unsigned long long b2 = pack2(b, b);
            #pragma unroll
            for (int i = 0; i < 4; ++i) fma2(acc[i][j], a2[i], b2);
        }
    }

    // ---- epilogue: fuse weight gather + scaled add, coalesced stores ----
    #pragma unroll
    for (int i = 0; i < 4; ++i) {
        const int tl = t0 + 2 * i;
        const long tokA = toks[tl];
        const long tokB = toks[tl + 1];
        float*       o0 = out + (long)(tBase + tl) * DIM + dBase + tx;
        float*       o1 = o0 + DIM;
        const float* w0 = W + tokA * DIM + dBase + tx;
        const float* w1 = W + tokB * DIM + dBase + tx;
        #pragma unroll
        for (int j = 0; j < 8; ++j) {
            float lo, hi;
            asm("mov.b64 {%0, %1}, %2;" : "=f"(lo), "=f"(hi) : "l"(acc[i][j]));
            o0[j * 32] = fmaf(16.0f, lo, w0[j * 32]);
            o1[j * 32] = fmaf(16.0f, hi, w1[j * 32]);
        }
    }
}

extern "C" void kernel_launch(void* const* d_in, const int* in_sizes, int n_in,
                              void* d_out, int out_size) {
    const int*   x  = (const int*)d_in[0];
    const float* W  = (const float*)d_in[1];
    const float* A  = (const float*)d_in[2];
    const float* Bm = (const float*)d_in[3];
    float* out = (float*)d_out;

    const int ntok = in_sizes[0];   // 16384

    const int smemBytes = (DC * BS_STRIDE + RNK * TC) * (int)sizeof(float)
                        + TC * (int)sizeof(int);   // 83,200 B
    cudaFuncSetAttribute(lora_embed_kernel,
                         cudaFuncAttributeMaxDynamicSharedMemorySize, smemBytes);

    dim3 grid(DIM / DC, ntok / TC);   // (8, 256)
    lora_embed_kernel<<<grid, NTHREADS, smemBytes>>>(x, W, A, Bm, out);
}

// round 4
// speedup vs baseline: 1.9463x; 1.9463x over previous
#include <cuda_runtime.h>
#include <cstdint>

#define VOCAB 50257
#define DIM   2048
#define RNK   64
#define MT    128            // tokens per CTA
#define NDC   128            // d-columns per chunk
#define NCHUNK (DIM / NDC)   // 16
#define NTHREADS 256

// B pre-transposed into mma fragment layout, per 128-col chunk (512 KB)
__device__ float g_Bfrag[DIM * RNK];

__device__ __forceinline__ uint32_t smem_u32(const void* p) {
    uint32_t a;
    asm("{ .reg .u64 t; cvta.to.shared.u64 t, %1; cvt.u32.u64 %0, t; }" : "=r"(a) : "l"(p));
    return a;
}
__device__ __forceinline__ uint32_t to_tf32(float v) {
    uint32_t r;
    asm("cvt.rna.tf32.f32 %0, %1;" : "=r"(r) : "f"(v));
    return r;
}
__device__ __forceinline__ void cpa16(uint32_t dst, const void* src) {
    asm volatile("cp.async.cg.shared.global [%0], [%1], 16;" :: "r"(dst), "l"(src));
}
__device__ __forceinline__ void mma_tf32(float* d, const float4& a, const float2& b) {
    asm volatile(
        "mma.sync.aligned.m16n8k8.row.col.f32.tf32.tf32.f32 "
        "{%0,%1,%2,%3}, {%4,%5,%6,%7}, {%8,%9}, {%0,%1,%2,%3};"
        : "+f"(d[0]), "+f"(d[1]), "+f"(d[2]), "+f"(d[3])
        : "r"(__float_as_uint(a.x)), "r"(__float_as_uint(a.y)),
          "r"(__float_as_uint(a.z)), "r"(__float_as_uint(a.w)),
          "r"(__float_as_uint(b.x)), "r"(__float_as_uint(b.y)));
}

// ---- prep: Bm[d][r] (f32) -> tf32 fragment layout, per 128-d chunk ----
// frag slot for (n = d&127, r): s=r>>3, kq=r&7, nt=n>>3, n8=n&7
//   lane = n8*4 + (kq&3), reg = kq>>2
//   idx  = chunk*8192 + ((s*16+nt)*32 + lane)*2 + reg
__global__ void prep_B(const float* __restrict__ Bm) {
    int idx = blockIdx.x * blockDim.x + threadIdx.x;   // 0..131071
    int d = idx >> 6, r = idx & 63;
    uint32_t tv = to_tf32(Bm[idx]);
    int chunk = d >> 7, n = d & 127;
    int s = r >> 3, kq = r & 7;
    int nt = n >> 3, n8 = n & 7;
    int lane = n8 * 4 + (kq & 3), reg = kq >> 2;
    g_Bfrag[chunk * 8192 + ((s * 16 + nt) * 32 + lane) * 2 + reg] = __uint_as_float(tv);
}

// ---- main kernel: one CTA per 128-token tile, loops over 16 d-chunks ----
__global__ void __launch_bounds__(NTHREADS)
lora_main(const int* __restrict__ x,
          const float* __restrict__ W,
          const float* __restrict__ A,
          float* __restrict__ out) {
    extern __shared__ float sm[];
    float* As   = sm;             // 8192 floats: A fragments (32 KB)
    float* Bbuf = sm + 8192;      // 2 x 8192 floats: B ping-pong (64 KB)
    int*   toks = (int*)(sm + 24576);

    const int tid  = threadIdx.x;
    const int tBase = blockIdx.x * MT;

    if (tid < MT) toks[tid] = x[tBase + tid];

    // prefetch B chunk 0
    {
        const float* src = g_Bfrag;
        uint32_t dst = smem_u32(Bbuf);
        #pragma unroll
        for (int j = 0; j < 8; ++j) {
            int i4 = j * NTHREADS + tid;
            cpa16(dst + i4 * 16, src + i4 * 4);
        }
        asm volatile("cp.async.commit_group;");
    }
    __syncthreads();   // toks visible

    // ---- gather A into fragment layout ----
    // (t, r): s=r>>3, kq=r&7, mt=t>>4, grp=(t&15)&7, hi=(t&15)>>3
    //   lane = grp*4 + (kq&3), reg = (kq>>2)*2 + hi
    #pragma unroll 4
    for (int i = tid; i < MT * RNK; i += NTHREADS) {
        int t = i & (MT - 1);
        int r = i >> 7;
        uint32_t tv = to_tf32(A[(size_t)r * VOCAB + toks[t]]);
        int s = r >> 3, kq = r & 7;
        int mt = t >> 4, row16 = t & 15;
        int grp = row16 & 7, hi = row16 >> 3;
        int lane = grp * 4 + (kq & 3);
        int reg = (kq >> 2) * 2 + hi;
        As[((s * 8 + mt) * 32 + lane) * 4 + reg] = __uint_as_float(tv);
    }

    const int wid  = tid >> 5;
    const int lane = tid & 31;
    const int mg   = wid >> 2;        // 0..1 : 64-token half
    const int ng   = wid & 3;         // 0..3 : 32-col quarter
    const int grp  = lane >> 2;
    const int tig  = lane & 3;

    // token ids for this thread's 8 output rows (stable across chunks)
    int tok[4][2];
    int rowg[4];
    #pragma unroll
    for (int mt = 0; mt < 4; ++mt) {
        int r0 = mg * 64 + mt * 16 + grp;
        rowg[mt] = r0;
        tok[mt][0] = toks[r0];        // toks written before first __syncthreads
        tok[mt][1] = toks[r0 + 8];
    }

    #pragma unroll 1
    for (int c = 0; c < NCHUNK; ++c) {
        float* curB = Bbuf + (c & 1) * 8192;
        if (c + 1 < NCHUNK) {
            const float* src = g_Bfrag + (c + 1) * 8192;
            uint32_t dst = smem_u32(Bbuf + ((c + 1) & 1) * 8192);
            #pragma unroll
            for (int j = 0; j < 8; ++j) {
                int i4 = j * NTHREADS + tid;
                cpa16(dst + i4 * 16, src + i4 * 4);
            }
            asm volatile("cp.async.commit_group;");
            asm volatile("cp.async.wait_group 1;");
        } else {
            asm volatile("cp.async.wait_group 0;");
        }
        __syncthreads();   // B[cur] ready for all; also A frags (c==0)

        // ---- MMA: warp tile m64 x n32, K=64 ----
        float acc[4][4][4];
        #pragma unroll
        for (int mt = 0; mt < 4; ++mt)
            #pragma unroll
            for (int nt = 0; nt < 4; ++nt)
                #pragma unroll
                for (int k = 0; k < 4; ++k) acc[mt][nt][k] = 0.f;

        #pragma unroll
        for (int s = 0; s < 8; ++s) {
            float4 a[4];
            float2 b[4];
            #pragma unroll
            for (int mt = 0; mt < 4; ++mt)
                a[mt] = *(const float4*)&As[((s * 8 + mg * 4 + mt) * 32 + lane) * 4];
            #pragma unroll
            for (int nt = 0; nt < 4; ++nt)
                b[nt] = *(const float2*)&curB[((s * 16 + ng * 4 + nt) * 32 + lane) * 2];
            #pragma unroll
            for (int mt = 0; mt < 4; ++mt)
                #pragma unroll
                for (int nt = 0; nt < 4; ++nt)
                    mma_tf32(acc[mt][nt], a[mt], b[nt]);
        }
        __syncthreads();   // mma reads done before next prefetch overwrites

        // ---- fused epilogue: W gather + 16*lora + store ----
        const int col0 = c * NDC + ng * 32 + 2 * tig;
        #pragma unroll
        for (int mt = 0; mt < 4; ++mt) {
            const float* w0 = W + (size_t)tok[mt][0] * DIM + col0;
            const float* w1 = W + (size_t)tok[mt][1] * DIM + col0;
            float* o0 = out + (size_t)(tBase + rowg[mt]) * DIM + col0;
            float* o1 = o0 + (size_t)8 * DIM;
            float2 wv0[4], wv1[4];
            #pragma unroll
            for (int nt = 0; nt < 4; ++nt) {
                wv0[nt] = *(const float2*)(w0 + nt * 8);
                wv1[nt] = *(const float2*)(w1 + nt * 8);
            }
            #pragma unroll
            for (int nt = 0; nt < 4; ++nt) {
                float2 r0, r1;
                r0.x = fmaf(16.f, acc[mt][nt][0], wv0[nt].x);
                r0.y = fmaf(16.f, acc[mt][nt][1], wv0[nt].y);
                r1.x = fmaf(16.f, acc[mt][nt][2], wv1[nt].x);
                r1.y = fmaf(16.f, acc[mt][nt][3], wv1[nt].y);
                *(float2*)(o0 + nt * 8) = r0;
                *(float2*)(o1 + nt * 8) = r1;
            }
        }
    }
}

extern "C" void kernel_launch(void* const* d_in, const int* in_sizes, int n_in,
                              void* d_out, int out_size) {
    const int*   x  = (const int*)d_in[0];
    const float* W  = (const float*)d_in[1];
    const float* A  = (const float*)d_in[2];
    const float* Bm = (const float*)d_in[3];
    float* out = (float*)d_out;

    const int ntok = in_sizes[0];   // 16384

    const int smemBytes = 24576 * 4 + MT * 4;   // 98816 B
    cudaFuncSetAttribute(lora_main,
                         cudaFuncAttributeMaxDynamicSharedMemorySize, smemBytes);

    prep_B<<<(DIM * RNK) / NTHREADS, NTHREADS>>>(Bm);
    lora_main<<<ntok / MT, NTHREADS, smemBytes>>>(x, W, A, out);
}